// round 1
// baseline (speedup 1.0000x reference)
#include <cuda_runtime.h>
#include <math.h>

// Problem constants
#define Bb 128
#define NQ 256
#define NC 128
#define D  1024
#define AD 256   // attn_dim
#define HD 128   // attn_dim/2
#define MD 512   // 2*attn_dim

// ---------------- scratch (device globals: no runtime allocation) ----------------
__device__ float g_S[Bb * NC * NQ];          // attn logits (post leaky), (B,NC,NQ)
__device__ float g_invn[Bb * NC];            // 1/(||row||+eps) over q
__device__ float g_attn[Bb * NQ * NC];       // softmaxed attn (B,NQ,NC)
__device__ float g_wc[Bb * NQ * D];          // weighted context
__device__ float g_matrix[Bb * NQ * D];      // evolving matrix
__device__ float g_smooth[Bb * NQ];          // evolving smooth
__device__ float g_common[Bb * NQ * AD];     // similarity features
__device__ float g_h1[Bb * NQ * MD];         // matrix-MLP hidden
__device__ float g_sh[Bb * NQ * HD];         // smooth-MLP hidden

// ---------------- utils ----------------
__device__ __forceinline__ float warp_sum(float v) {
#pragma unroll
    for (int o = 16; o > 0; o >>= 1) v += __shfl_xor_sync(0xffffffffu, v, o);
    return v;
}

// ---------------- init: matrix = 1, smooth = 10 ----------------
__global__ void init_kernel(float* __restrict__ matrix, float* __restrict__ smooth) {
    size_t i = (size_t)blockIdx.x * blockDim.x + threadIdx.x;
    if (i < (size_t)Bb * NQ * D) matrix[i] = 1.0f;
    if (i < (size_t)Bb * NQ) smooth[i] = 10.0f;
}

// ---------------- GEMM S = leakyrelu( ctx[b] @ (query*matrix)[b]^T ) ----------------
// per batch: M=NC=128, N=NQ=256, K=D=1024.  Block tile 128x128, 256 thr, 8x8 microtile.
__global__ void __launch_bounds__(256) gemm_s_kernel(
    const float* __restrict__ ctx, const float* __restrict__ query,
    const float* __restrict__ matrix, float* __restrict__ S)
{
    const int b  = blockIdx.y;
    const int n0 = blockIdx.x * 128;
    const float* A  = ctx    + (size_t)b * NC * D;
    const float* Q  = query  + (size_t)b * NQ * D + (size_t)n0 * D;
    const float* Mx = matrix + (size_t)b * NQ * D + (size_t)n0 * D;

    __shared__ float As[16][128];
    __shared__ float Bs[16][128];

    const int tid = threadIdx.x;
    const int tx = tid & 15, ty = tid >> 4;
    const int lr = tid >> 1;            // 0..127 (row within tile)
    const int lk = (tid & 1) * 8;       // 0 or 8

    float acc[8][8];
#pragma unroll
    for (int i = 0; i < 8; i++)
#pragma unroll
        for (int j = 0; j < 8; j++) acc[i][j] = 0.0f;

    for (int k0 = 0; k0 < D; k0 += 16) {
        float4 a0 = *(const float4*)(A + (size_t)lr * D + k0 + lk);
        float4 a1 = *(const float4*)(A + (size_t)lr * D + k0 + lk + 4);
        float4 q0 = *(const float4*)(Q + (size_t)lr * D + k0 + lk);
        float4 q1 = *(const float4*)(Q + (size_t)lr * D + k0 + lk + 4);
        float4 m0 = *(const float4*)(Mx + (size_t)lr * D + k0 + lk);
        float4 m1 = *(const float4*)(Mx + (size_t)lr * D + k0 + lk + 4);

        As[lk + 0][lr] = a0.x; As[lk + 1][lr] = a0.y; As[lk + 2][lr] = a0.z; As[lk + 3][lr] = a0.w;
        As[lk + 4][lr] = a1.x; As[lk + 5][lr] = a1.y; As[lk + 6][lr] = a1.z; As[lk + 7][lr] = a1.w;
        Bs[lk + 0][lr] = q0.x * m0.x; Bs[lk + 1][lr] = q0.y * m0.y;
        Bs[lk + 2][lr] = q0.z * m0.z; Bs[lk + 3][lr] = q0.w * m0.w;
        Bs[lk + 4][lr] = q1.x * m1.x; Bs[lk + 5][lr] = q1.y * m1.y;
        Bs[lk + 6][lr] = q1.z * m1.z; Bs[lk + 7][lr] = q1.w * m1.w;
        __syncthreads();

#pragma unroll
        for (int k = 0; k < 16; k++) {
            float af[8], bf[8];
#pragma unroll
            for (int i = 0; i < 8; i++) af[i] = As[k][ty * 8 + i];
#pragma unroll
            for (int j = 0; j < 8; j++) bf[j] = Bs[k][tx * 8 + j];
#pragma unroll
            for (int i = 0; i < 8; i++)
#pragma unroll
                for (int j = 0; j < 8; j++) acc[i][j] += af[i] * bf[j];
        }
        __syncthreads();
    }

    float* Sp = S + (size_t)b * NC * NQ;
#pragma unroll
    for (int i = 0; i < 8; i++) {
        int m = ty * 8 + i;
#pragma unroll
        for (int j = 0; j < 8; j++) {
            float v = acc[i][j];
            v = (v >= 0.0f) ? v : 0.1f * v;   // LeakyReLU(0.1)
            Sp[(size_t)m * NQ + n0 + tx * 8 + j] = v;
        }
    }
}

// ---------------- generic NN GEMM: C = epi(A @ B + bias), optional batching ----------------
// AMODE: 0 plain A load, 1 A element = (A - A2)^2
// EPI:   0 store, 1 tanh-store, 2 matrix-update in `extra` (clip(tanh(v)+old,-1,1))
template<int AMODE, int EPI>
__global__ void __launch_bounds__(256) gemm_nn_kernel(
    const float* __restrict__ A, const float* __restrict__ A2,
    const float* __restrict__ Bw, const float* __restrict__ bias,
    float* __restrict__ C, float* __restrict__ extra,
    int N, int K, size_t sA, size_t sB, size_t sC)
{
    const int bz = blockIdx.z;
    const float* Ab  = A + (size_t)bz * sA;
    const float* A2b = (AMODE == 1) ? (A2 + (size_t)bz * sA) : nullptr;
    const float* Bb_ = Bw + (size_t)bz * sB;
    float* Cb = C + (size_t)bz * sC;

    const int m0 = blockIdx.y * 128, n0 = blockIdx.x * 128;

    __shared__ float As[16][128];
    __shared__ float Bs[16][128];

    const int tid = threadIdx.x;
    const int tx = tid & 15, ty = tid >> 4;
    const int lr = tid >> 1, lk = (tid & 1) * 8;        // A load mapping
    const int bk = tid >> 4, bn = (tid & 15) * 8;       // B load mapping

    float acc[8][8];
#pragma unroll
    for (int i = 0; i < 8; i++)
#pragma unroll
        for (int j = 0; j < 8; j++) acc[i][j] = 0.0f;

    for (int k0 = 0; k0 < K; k0 += 16) {
        const float* ap = Ab + (size_t)(m0 + lr) * K + k0 + lk;
        float4 a0 = *(const float4*)ap;
        float4 a1 = *(const float4*)(ap + 4);
        if (AMODE == 1) {
            const float* wp = A2b + (size_t)(m0 + lr) * K + k0 + lk;
            float4 w0 = *(const float4*)wp;
            float4 w1 = *(const float4*)(wp + 4);
            a0.x -= w0.x; a0.y -= w0.y; a0.z -= w0.z; a0.w -= w0.w;
            a1.x -= w1.x; a1.y -= w1.y; a1.z -= w1.z; a1.w -= w1.w;
            a0.x *= a0.x; a0.y *= a0.y; a0.z *= a0.z; a0.w *= a0.w;
            a1.x *= a1.x; a1.y *= a1.y; a1.z *= a1.z; a1.w *= a1.w;
        }
        As[lk + 0][lr] = a0.x; As[lk + 1][lr] = a0.y; As[lk + 2][lr] = a0.z; As[lk + 3][lr] = a0.w;
        As[lk + 4][lr] = a1.x; As[lk + 5][lr] = a1.y; As[lk + 6][lr] = a1.z; As[lk + 7][lr] = a1.w;

        const float* bp = Bb_ + (size_t)(k0 + bk) * N + n0 + bn;
        float4 b0 = *(const float4*)bp;
        float4 b1 = *(const float4*)(bp + 4);
        *(float4*)&Bs[bk][bn]     = b0;
        *(float4*)&Bs[bk][bn + 4] = b1;
        __syncthreads();

#pragma unroll
        for (int k = 0; k < 16; k++) {
            float af[8], bf[8];
#pragma unroll
            for (int i = 0; i < 8; i++) af[i] = As[k][ty * 8 + i];
#pragma unroll
            for (int j = 0; j < 8; j++) bf[j] = Bs[k][tx * 8 + j];
#pragma unroll
            for (int i = 0; i < 8; i++)
#pragma unroll
                for (int j = 0; j < 8; j++) acc[i][j] += af[i] * bf[j];
        }
        __syncthreads();
    }

#pragma unroll
    for (int i = 0; i < 8; i++) {
        int mg = m0 + ty * 8 + i;
#pragma unroll
        for (int j = 0; j < 8; j++) {
            int ng = n0 + tx * 8 + j;
            float v = acc[i][j];
            if (bias != nullptr) v += bias[ng];
            if (EPI == 1) v = tanhf(v);
            if (EPI == 2) {
                size_t idx = (size_t)mg * N + ng;
                float nv = tanhf(v) + extra[idx];
                nv = fminf(1.0f, fmaxf(-1.0f, nv));
                extra[idx] = nv;
            } else {
                Cb[(size_t)mg * N + ng] = v;
            }
        }
    }
}

// ---------------- row L2 norm (over q) of S: invn[b,c] = 1/(||S[b,c,:]||+eps) ----------------
__global__ void rownorm_kernel(const float* __restrict__ S, float* __restrict__ invn) {
    int bc = blockIdx.x;
    float v = S[(size_t)bc * NQ + threadIdx.x];
    float s = warp_sum(v * v);
    __shared__ float red[8];
    if ((threadIdx.x & 31) == 0) red[threadIdx.x >> 5] = s;
    __syncthreads();
    if (threadIdx.x == 0) {
        float t = red[0] + red[1] + red[2] + red[3] + red[4] + red[5] + red[6] + red[7];
        invn[bc] = 1.0f / (sqrtf(t) + 1e-8f);
    }
}

// ---------------- softmax over c with per-(b,q) smooth; transposes S -> attn ----------------
__global__ void __launch_bounds__(256) softmax_kernel(
    const float* __restrict__ S, const float* __restrict__ invn,
    const float* __restrict__ smooth, float* __restrict__ attn)
{
    int b = blockIdx.y;
    int q0 = blockIdx.x * 32;
    __shared__ float sm[NC][33];
    const float* Sb = S + (size_t)b * NC * NQ;
    for (int idx = threadIdx.x; idx < NC * 32; idx += 256) {
        int c = idx >> 5, qq = idx & 31;
        sm[c][qq] = Sb[(size_t)c * NQ + q0 + qq] * invn[b * NC + c];
    }
    __syncthreads();
    int warp = threadIdx.x >> 5, lane = threadIdx.x & 31;
    for (int qi = warp; qi < 32; qi += 8) {
        float sf = smooth[b * NQ + q0 + qi];
        float v0 = sm[lane][qi] * sf;
        float v1 = sm[lane + 32][qi] * sf;
        float v2 = sm[lane + 64][qi] * sf;
        float v3 = sm[lane + 96][qi] * sf;
        float mx = fmaxf(fmaxf(v0, v1), fmaxf(v2, v3));
#pragma unroll
        for (int o = 16; o > 0; o >>= 1) mx = fmaxf(mx, __shfl_xor_sync(0xffffffffu, mx, o));
        float e0 = expf(v0 - mx), e1 = expf(v1 - mx), e2 = expf(v2 - mx), e3 = expf(v3 - mx);
        float s = warp_sum(e0 + e1 + e2 + e3);
        float inv = 1.0f / s;
        float* ap = attn + ((size_t)b * NQ + q0 + qi) * NC;
        ap[lane] = e0 * inv; ap[lane + 32] = e1 * inv;
        ap[lane + 64] = e2 * inv; ap[lane + 96] = e3 * inv;
    }
}

// ---------------- in-place L2 norm over last dim (256) ----------------
__global__ void l2norm256_kernel(float* __restrict__ X) {
    float* p = X + (size_t)blockIdx.x * AD;
    float v = p[threadIdx.x];
    float s = warp_sum(v * v);
    __shared__ float red[8];
    if ((threadIdx.x & 31) == 0) red[threadIdx.x >> 5] = s;
    __syncthreads();
    float t = red[0] + red[1] + red[2] + red[3] + red[4] + red[5] + red[6] + red[7];
    p[threadIdx.x] = v / (sqrtf(t) + 1e-8f);
}

// ---------------- smooth update: smooth = relu(sh . w2 + b2 + smooth) ----------------
__global__ void sw_reduce_kernel(const float* __restrict__ sh, const float* __restrict__ w2,
                                 const float* __restrict__ b2, float* __restrict__ smooth)
{
    int row = blockIdx.x * 8 + (threadIdx.x >> 5);
    int lane = threadIdx.x & 31;
    const float* r = sh + (size_t)row * HD;
    float s = r[lane] * w2[lane] + r[lane + 32] * w2[lane + 32]
            + r[lane + 64] * w2[lane + 64] + r[lane + 96] * w2[lane + 96];
    s = warp_sum(s);
    if (lane == 0) smooth[row] = fmaxf(0.0f, s + b2[0] + smooth[row]);
}

// ---------------- orchestration ----------------
extern "C" void kernel_launch(void* const* d_in, const int* in_sizes, int n_in,
                              void* d_out, int out_size)
{
    const float* query = (const float*)d_in[0];
    const float* ctx   = (const float*)d_in[1];
    const float* cw_W  = (const float*)d_in[2];
    const float* cw_b  = (const float*)d_in[3];
    const float* sw_W1 = (const float*)d_in[4];
    const float* sw_b1 = (const float*)d_in[5];
    const float* sw_W2 = (const float*)d_in[6];
    const float* sw_b2 = (const float*)d_in[7];
    const float* mw_W1 = (const float*)d_in[8];
    const float* mw_b1 = (const float*)d_in[9];
    const float* mw_W2 = (const float*)d_in[10];
    const float* mw_b2 = (const float*)d_in[11];

    float* out      = (float*)d_out;
    float* out_q    = out;
    float* out_wc   = out + (size_t)Bb * NQ * D;
    float* out_attn = out + 2 * (size_t)Bb * NQ * D;

    float *pS, *pinvn, *pattn, *pwc, *pmat, *psm, *pcom, *ph1, *psh;
    cudaGetSymbolAddress((void**)&pS,    g_S);
    cudaGetSymbolAddress((void**)&pinvn, g_invn);
    cudaGetSymbolAddress((void**)&pattn, g_attn);
    cudaGetSymbolAddress((void**)&pwc,   g_wc);
    cudaGetSymbolAddress((void**)&pmat,  g_matrix);
    cudaGetSymbolAddress((void**)&psm,   g_smooth);
    cudaGetSymbolAddress((void**)&pcom,  g_common);
    cudaGetSymbolAddress((void**)&ph1,   g_h1);
    cudaGetSymbolAddress((void**)&psh,   g_sh);

    init_kernel<<<(Bb * NQ * D + 255) / 256, 256>>>(pmat, psm);

    for (int i = 0; i < 2; i++) {
        // attention scan
        gemm_s_kernel<<<dim3(2, 128), 256>>>(ctx, query, pmat, pS);
        rownorm_kernel<<<Bb * NC, 256>>>(pS, pinvn);
        softmax_kernel<<<dim3(8, 128), 256>>>(pS, pinvn, psm, pattn);
        gemm_nn_kernel<0, 0><<<dim3(8, 2, 128), 256>>>(
            pattn, nullptr, ctx, nullptr, pwc, nullptr,
            D, NC, (size_t)NQ * NC, (size_t)NC * D, (size_t)NQ * D);

        // common = l2norm((q - wc)^2 @ cw_W + cw_b)
        gemm_nn_kernel<1, 0><<<dim3(2, 256, 1), 256>>>(
            query, pwc, cw_W + (size_t)i * D * AD, cw_b + (size_t)i * AD,
            pcom, nullptr, AD, D, 0, 0, 0);
        l2norm256_kernel<<<Bb * NQ, 256>>>(pcom);

        // smooth branch
        gemm_nn_kernel<0, 1><<<dim3(1, 256, 1), 256>>>(
            pcom, nullptr, sw_W1 + (size_t)i * AD * HD, sw_b1 + (size_t)i * HD,
            psh, nullptr, HD, AD, 0, 0, 0);
        sw_reduce_kernel<<<Bb * NQ / 8, 256>>>(psh, sw_W2 + (size_t)i * HD, sw_b2 + i, psm);

        // matrix branch
        gemm_nn_kernel<0, 1><<<dim3(4, 256, 1), 256>>>(
            pcom, nullptr, mw_W1 + (size_t)i * AD * MD, mw_b1 + (size_t)i * MD,
            ph1, nullptr, MD, AD, 0, 0, 0);
        gemm_nn_kernel<0, 2><<<dim3(8, 256, 1), 256>>>(
            ph1, nullptr, mw_W2 + (size_t)i * MD * D, mw_b2 + (size_t)i * D,
            pmat, pmat, D, MD, 0, 0, 0);
    }

    // final attention scan, writing attn and wc straight into d_out
    gemm_s_kernel<<<dim3(2, 128), 256>>>(ctx, query, pmat, pS);
    rownorm_kernel<<<Bb * NC, 256>>>(pS, pinvn);
    softmax_kernel<<<dim3(8, 128), 256>>>(pS, pinvn, psm, out_attn);
    gemm_nn_kernel<0, 0><<<dim3(8, 2, 128), 256>>>(
        out_attn, nullptr, ctx, nullptr, out_wc, nullptr,
        D, NC, (size_t)NQ * NC, (size_t)NC * D, (size_t)NQ * D);

    cudaMemcpyAsync(out_q, query, (size_t)Bb * NQ * D * sizeof(float),
                    cudaMemcpyDeviceToDevice, 0);
}

// round 2
// speedup vs baseline: 1.8407x; 1.8407x over previous
#include <cuda_runtime.h>
#include <stdint.h>
#include <math.h>

// Problem constants
#define Bb 128
#define NQ 256
#define NC 128
#define D  1024
#define AD 256   // attn_dim
#define HD 128   // attn_dim/2
#define MD 512   // 2*attn_dim

// ---------------- scratch (device globals: no runtime allocation) ----------------
__device__ float g_S[Bb * NC * NQ];
__device__ float g_invn[Bb * NC];
__device__ float g_attn[Bb * NQ * NC];
__device__ float g_wc[Bb * NQ * D];
__device__ float g_matrix[Bb * NQ * D];
__device__ float g_smooth[Bb * NQ];
__device__ float g_common[Bb * NQ * AD];
__device__ float g_h1[Bb * NQ * MD];
__device__ float g_sh[Bb * NQ * HD];

// ---------------- utils ----------------
__device__ __forceinline__ float warp_sum(float v) {
#pragma unroll
    for (int o = 16; o > 0; o >>= 1) v += __shfl_xor_sync(0xffffffffu, v, o);
    return v;
}

__device__ __forceinline__ uint32_t f2tf(float x) {
    uint32_t r;
    asm("cvt.rna.tf32.f32 %0, %1;" : "=r"(r) : "f"(x));
    return r;
}

__device__ __forceinline__ void mma_tf32(float* c, const uint32_t* a, const uint32_t* b) {
    asm volatile(
        "mma.sync.aligned.m16n8k8.row.col.f32.tf32.tf32.f32 "
        "{%0,%1,%2,%3},{%4,%5,%6,%7},{%8,%9},{%0,%1,%2,%3};"
        : "+f"(c[0]), "+f"(c[1]), "+f"(c[2]), "+f"(c[3])
        : "r"(a[0]), "r"(a[1]), "r"(a[2]), "r"(a[3]), "r"(b[0]), "r"(b[1]));
}

// smem strides (pad for conflict reduction)
#define SSTR 17

// ---------------- init: matrix = 1, smooth = 10 ----------------
__global__ void init_kernel(float* __restrict__ matrix, float* __restrict__ smooth) {
    size_t i = (size_t)blockIdx.x * blockDim.x + threadIdx.x;
    if (i < (size_t)Bb * NQ * D) matrix[i] = 1.0f;
    if (i < (size_t)Bb * NQ) smooth[i] = 10.0f;
}

// ---------------- S = leakyrelu( ctx[b] @ (query*matrix)[b]^T ) -----------------
// per batch: M=NC=128, N(tile)=128 of NQ=256, K=D=1024. 256 thr, 8 warps (4M x 2N),
// warp tile 32x64, m16n8k8 tf32 MMA.
__global__ void __launch_bounds__(256) gemm_s_kernel(
    const float* __restrict__ ctx, const float* __restrict__ query,
    const float* __restrict__ matrix, float* __restrict__ S)
{
    const int b  = blockIdx.y;
    const int n0 = blockIdx.x * 128;
    const float* A  = ctx    + (size_t)b * NC * D;
    const float* Q  = query  + (size_t)b * NQ * D + (size_t)n0 * D;
    const float* Mx = matrix + (size_t)b * NQ * D + (size_t)n0 * D;

    __shared__ uint32_t AsU[128 * SSTR];
    __shared__ uint32_t BsU[128 * SSTR];

    const int tid  = threadIdx.x;
    const int warp = tid >> 5, lane = tid & 31;
    const int g = lane >> 2, tg = lane & 3;
    const int wm = (warp & 3) * 32;
    const int wn = (warp >> 2) * 64;
    const int lr = tid >> 1, lk = (tid & 1) * 8;

    float acc[2][8][4];
#pragma unroll
    for (int i = 0; i < 2; i++)
#pragma unroll
        for (int j = 0; j < 8; j++)
#pragma unroll
            for (int r = 0; r < 4; r++) acc[i][j][r] = 0.0f;

    for (int k0 = 0; k0 < D; k0 += 16) {
        float4 a0 = *(const float4*)(A + (size_t)lr * D + k0 + lk);
        float4 a1 = *(const float4*)(A + (size_t)lr * D + k0 + lk + 4);
        float4 q0 = *(const float4*)(Q + (size_t)lr * D + k0 + lk);
        float4 q1 = *(const float4*)(Q + (size_t)lr * D + k0 + lk + 4);
        float4 m0 = *(const float4*)(Mx + (size_t)lr * D + k0 + lk);
        float4 m1 = *(const float4*)(Mx + (size_t)lr * D + k0 + lk + 4);

        uint32_t* ar = AsU + lr * SSTR + lk;
        ar[0] = f2tf(a0.x); ar[1] = f2tf(a0.y); ar[2] = f2tf(a0.z); ar[3] = f2tf(a0.w);
        ar[4] = f2tf(a1.x); ar[5] = f2tf(a1.y); ar[6] = f2tf(a1.z); ar[7] = f2tf(a1.w);
        uint32_t* br = BsU + lr * SSTR + lk;
        br[0] = f2tf(q0.x * m0.x); br[1] = f2tf(q0.y * m0.y);
        br[2] = f2tf(q0.z * m0.z); br[3] = f2tf(q0.w * m0.w);
        br[4] = f2tf(q1.x * m1.x); br[5] = f2tf(q1.y * m1.y);
        br[6] = f2tf(q1.z * m1.z); br[7] = f2tf(q1.w * m1.w);
        __syncthreads();

#pragma unroll
        for (int kk = 0; kk < 16; kk += 8) {
            uint32_t af[2][4];
#pragma unroll
            for (int mi = 0; mi < 2; mi++) {
                int r = wm + mi * 16;
                af[mi][0] = AsU[(r + g) * SSTR + kk + tg];
                af[mi][1] = AsU[(r + 8 + g) * SSTR + kk + tg];
                af[mi][2] = AsU[(r + g) * SSTR + kk + tg + 4];
                af[mi][3] = AsU[(r + 8 + g) * SSTR + kk + tg + 4];
            }
            uint32_t bf[8][2];
#pragma unroll
            for (int ni = 0; ni < 8; ni++) {
                int c = wn + ni * 8 + g;
                bf[ni][0] = BsU[c * SSTR + kk + tg];
                bf[ni][1] = BsU[c * SSTR + kk + tg + 4];
            }
#pragma unroll
            for (int mi = 0; mi < 2; mi++)
#pragma unroll
                for (int ni = 0; ni < 8; ni++)
                    mma_tf32(acc[mi][ni], af[mi], bf[ni]);
        }
        __syncthreads();
    }

    float* Sp = S + (size_t)b * NC * NQ;
#pragma unroll
    for (int mi = 0; mi < 2; mi++) {
        int r0 = wm + mi * 16 + g;
#pragma unroll
        for (int ni = 0; ni < 8; ni++) {
            int cc = n0 + wn + ni * 8 + 2 * tg;
            float v;
            v = acc[mi][ni][0]; v = (v >= 0.f) ? v : 0.1f * v; Sp[(size_t)r0 * NQ + cc] = v;
            v = acc[mi][ni][1]; v = (v >= 0.f) ? v : 0.1f * v; Sp[(size_t)r0 * NQ + cc + 1] = v;
            v = acc[mi][ni][2]; v = (v >= 0.f) ? v : 0.1f * v; Sp[(size_t)(r0 + 8) * NQ + cc] = v;
            v = acc[mi][ni][3]; v = (v >= 0.f) ? v : 0.1f * v; Sp[(size_t)(r0 + 8) * NQ + cc + 1] = v;
        }
    }
}

// ---------------- generic NN GEMM: C = epi(A @ B + bias) ----------------
// AMODE: 0 plain A, 1 A element = (A - A2)^2
// EPI:   0 store, 1 tanh-store, 2 matrix-update in `extra` (clip(tanh(v)+old,-1,1))
template<int AMODE, int EPI>
__global__ void __launch_bounds__(256) gemm_nn_kernel(
    const float* __restrict__ A, const float* __restrict__ A2,
    const float* __restrict__ Bw, const float* __restrict__ bias,
    float* __restrict__ C, float* __restrict__ extra,
    int N, int K, size_t sA, size_t sB, size_t sC)
{
    const int bz = blockIdx.z;
    const float* Ab  = A + (size_t)bz * sA;
    const float* A2b = (AMODE == 1) ? (A2 + (size_t)bz * sA) : nullptr;
    const float* Bp  = Bw + (size_t)bz * sB;
    float* Cb = C + (size_t)bz * sC;

    const int m0 = blockIdx.y * 128, n0 = blockIdx.x * 128;

    __shared__ uint32_t AsU[128 * SSTR];
    __shared__ uint32_t BsU[128 * SSTR];

    const int tid  = threadIdx.x;
    const int warp = tid >> 5, lane = tid & 31;
    const int g = lane >> 2, tg = lane & 3;
    const int wm = (warp & 3) * 32;
    const int wn = (warp >> 2) * 64;
    const int lr = tid >> 1, lk = (tid & 1) * 8;   // A load mapping
    const int bn = tid & 127, bk = (tid >> 7) * 8; // B transpose-load mapping

    float acc[2][8][4];
#pragma unroll
    for (int i = 0; i < 2; i++)
#pragma unroll
        for (int j = 0; j < 8; j++)
#pragma unroll
            for (int r = 0; r < 4; r++) acc[i][j][r] = 0.0f;

    for (int k0 = 0; k0 < K; k0 += 16) {
        const float* ap = Ab + (size_t)(m0 + lr) * K + k0 + lk;
        float4 a0 = *(const float4*)ap;
        float4 a1 = *(const float4*)(ap + 4);
        if (AMODE == 1) {
            const float* wp = A2b + (size_t)(m0 + lr) * K + k0 + lk;
            float4 w0 = *(const float4*)wp;
            float4 w1 = *(const float4*)(wp + 4);
            a0.x -= w0.x; a0.y -= w0.y; a0.z -= w0.z; a0.w -= w0.w;
            a1.x -= w1.x; a1.y -= w1.y; a1.z -= w1.z; a1.w -= w1.w;
            a0.x *= a0.x; a0.y *= a0.y; a0.z *= a0.z; a0.w *= a0.w;
            a1.x *= a1.x; a1.y *= a1.y; a1.z *= a1.z; a1.w *= a1.w;
        }
        uint32_t* ar = AsU + lr * SSTR + lk;
        ar[0] = f2tf(a0.x); ar[1] = f2tf(a0.y); ar[2] = f2tf(a0.z); ar[3] = f2tf(a0.w);
        ar[4] = f2tf(a1.x); ar[5] = f2tf(a1.y); ar[6] = f2tf(a1.z); ar[7] = f2tf(a1.w);

        // B: global [K][N] row-major -> smem [n][k]
#pragma unroll
        for (int i = 0; i < 8; i++) {
            float bv = Bp[(size_t)(k0 + bk + i) * N + n0 + bn];
            BsU[bn * SSTR + bk + i] = f2tf(bv);
        }
        __syncthreads();

#pragma unroll
        for (int kk = 0; kk < 16; kk += 8) {
            uint32_t af[2][4];
#pragma unroll
            for (int mi = 0; mi < 2; mi++) {
                int r = wm + mi * 16;
                af[mi][0] = AsU[(r + g) * SSTR + kk + tg];
                af[mi][1] = AsU[(r + 8 + g) * SSTR + kk + tg];
                af[mi][2] = AsU[(r + g) * SSTR + kk + tg + 4];
                af[mi][3] = AsU[(r + 8 + g) * SSTR + kk + tg + 4];
            }
            uint32_t bf[8][2];
#pragma unroll
            for (int ni = 0; ni < 8; ni++) {
                int c = wn + ni * 8 + g;
                bf[ni][0] = BsU[c * SSTR + kk + tg];
                bf[ni][1] = BsU[c * SSTR + kk + tg + 4];
            }
#pragma unroll
            for (int mi = 0; mi < 2; mi++)
#pragma unroll
                for (int ni = 0; ni < 8; ni++)
                    mma_tf32(acc[mi][ni], af[mi], bf[ni]);
        }
        __syncthreads();
    }

#pragma unroll
    for (int mi = 0; mi < 2; mi++) {
        int r0 = m0 + wm + mi * 16 + g;
#pragma unroll
        for (int ni = 0; ni < 8; ni++) {
            int cg = n0 + wn + ni * 8 + 2 * tg;
#pragma unroll
            for (int half = 0; half < 2; half++) {
                int mg = r0 + half * 8;
#pragma unroll
                for (int jj = 0; jj < 2; jj++) {
                    int ng = cg + jj;
                    float v = acc[mi][ni][half * 2 + jj];
                    if (bias != nullptr) v += bias[ng];
                    if (EPI == 1) v = tanhf(v);
                    if (EPI == 2) {
                        size_t idx = (size_t)mg * N + ng;
                        float nv = tanhf(v) + extra[idx];
                        nv = fminf(1.0f, fmaxf(-1.0f, nv));
                        extra[idx] = nv;
                    } else {
                        Cb[(size_t)mg * N + ng] = v;
                    }
                }
            }
        }
    }
}

// ---------------- row L2 norm (over q) of S ----------------
__global__ void rownorm_kernel(const float* __restrict__ S, float* __restrict__ invn) {
    int bc = blockIdx.x;
    float v = S[(size_t)bc * NQ + threadIdx.x];
    float s = warp_sum(v * v);
    __shared__ float red[8];
    if ((threadIdx.x & 31) == 0) red[threadIdx.x >> 5] = s;
    __syncthreads();
    if (threadIdx.x == 0) {
        float t = red[0] + red[1] + red[2] + red[3] + red[4] + red[5] + red[6] + red[7];
        invn[bc] = 1.0f / (sqrtf(t) + 1e-8f);
    }
}

// ---------------- softmax over c with per-(b,q) smooth; transposes S -> attn ----------------
__global__ void __launch_bounds__(256) softmax_kernel(
    const float* __restrict__ S, const float* __restrict__ invn,
    const float* __restrict__ smooth, float* __restrict__ attn)
{
    int b = blockIdx.y;
    int q0 = blockIdx.x * 32;
    __shared__ float sm[NC][33];
    const float* Sb = S + (size_t)b * NC * NQ;
    for (int idx = threadIdx.x; idx < NC * 32; idx += 256) {
        int c = idx >> 5, qq = idx & 31;
        sm[c][qq] = Sb[(size_t)c * NQ + q0 + qq] * invn[b * NC + c];
    }
    __syncthreads();
    int warp = threadIdx.x >> 5, lane = threadIdx.x & 31;
    for (int qi = warp; qi < 32; qi += 8) {
        float sf = smooth[b * NQ + q0 + qi];
        float v0 = sm[lane][qi] * sf;
        float v1 = sm[lane + 32][qi] * sf;
        float v2 = sm[lane + 64][qi] * sf;
        float v3 = sm[lane + 96][qi] * sf;
        float mx = fmaxf(fmaxf(v0, v1), fmaxf(v2, v3));
#pragma unroll
        for (int o = 16; o > 0; o >>= 1) mx = fmaxf(mx, __shfl_xor_sync(0xffffffffu, mx, o));
        float e0 = expf(v0 - mx), e1 = expf(v1 - mx), e2 = expf(v2 - mx), e3 = expf(v3 - mx);
        float s = warp_sum(e0 + e1 + e2 + e3);
        float inv = 1.0f / s;
        float* ap = attn + ((size_t)b * NQ + q0 + qi) * NC;
        ap[lane] = e0 * inv; ap[lane + 32] = e1 * inv;
        ap[lane + 64] = e2 * inv; ap[lane + 96] = e3 * inv;
    }
}

// ---------------- in-place L2 norm over last dim (256) ----------------
__global__ void l2norm256_kernel(float* __restrict__ X) {
    float* p = X + (size_t)blockIdx.x * AD;
    float v = p[threadIdx.x];
    float s = warp_sum(v * v);
    __shared__ float red[8];
    if ((threadIdx.x & 31) == 0) red[threadIdx.x >> 5] = s;
    __syncthreads();
    float t = red[0] + red[1] + red[2] + red[3] + red[4] + red[5] + red[6] + red[7];
    p[threadIdx.x] = v / (sqrtf(t) + 1e-8f);
}

// ---------------- smooth update: smooth = relu(sh . w2 + b2 + smooth) ----------------
__global__ void sw_reduce_kernel(const float* __restrict__ sh, const float* __restrict__ w2,
                                 const float* __restrict__ b2, float* __restrict__ smooth)
{
    int row = blockIdx.x * 8 + (threadIdx.x >> 5);
    int lane = threadIdx.x & 31;
    const float* r = sh + (size_t)row * HD;
    float s = r[lane] * w2[lane] + r[lane + 32] * w2[lane + 32]
            + r[lane + 64] * w2[lane + 64] + r[lane + 96] * w2[lane + 96];
    s = warp_sum(s);
    if (lane == 0) smooth[row] = fmaxf(0.0f, s + b2[0] + smooth[row]);
}

// ---------------- orchestration ----------------
extern "C" void kernel_launch(void* const* d_in, const int* in_sizes, int n_in,
                              void* d_out, int out_size)
{
    const float* query = (const float*)d_in[0];
    const float* ctx   = (const float*)d_in[1];
    const float* cw_W  = (const float*)d_in[2];
    const float* cw_b  = (const float*)d_in[3];
    const float* sw_W1 = (const float*)d_in[4];
    const float* sw_b1 = (const float*)d_in[5];
    const float* sw_W2 = (const float*)d_in[6];
    const float* sw_b2 = (const float*)d_in[7];
    const float* mw_W1 = (const float*)d_in[8];
    const float* mw_b1 = (const float*)d_in[9];
    const float* mw_W2 = (const float*)d_in[10];
    const float* mw_b2 = (const float*)d_in[11];

    float* out      = (float*)d_out;
    float* out_q    = out;
    float* out_wc   = out + (size_t)Bb * NQ * D;
    float* out_attn = out + 2 * (size_t)Bb * NQ * D;

    float *pS, *pinvn, *pattn, *pwc, *pmat, *psm, *pcom, *ph1, *psh;
    cudaGetSymbolAddress((void**)&pS,    g_S);
    cudaGetSymbolAddress((void**)&pinvn, g_invn);
    cudaGetSymbolAddress((void**)&pattn, g_attn);
    cudaGetSymbolAddress((void**)&pwc,   g_wc);
    cudaGetSymbolAddress((void**)&pmat,  g_matrix);
    cudaGetSymbolAddress((void**)&psm,   g_smooth);
    cudaGetSymbolAddress((void**)&pcom,  g_common);
    cudaGetSymbolAddress((void**)&ph1,   g_h1);
    cudaGetSymbolAddress((void**)&psh,   g_sh);

    init_kernel<<<(Bb * NQ * D + 255) / 256, 256>>>(pmat, psm);

    for (int i = 0; i < 2; i++) {
        // attention scan
        gemm_s_kernel<<<dim3(2, 128), 256>>>(ctx, query, pmat, pS);
        rownorm_kernel<<<Bb * NC, 256>>>(pS, pinvn);
        softmax_kernel<<<dim3(8, 128), 256>>>(pS, pinvn, psm, pattn);
        gemm_nn_kernel<0, 0><<<dim3(8, 2, 128), 256>>>(
            pattn, nullptr, ctx, nullptr, pwc, nullptr,
            D, NC, (size_t)NQ * NC, (size_t)NC * D, (size_t)NQ * D);

        // common = l2norm((q - wc)^2 @ cw_W + cw_b)
        gemm_nn_kernel<1, 0><<<dim3(2, 256, 1), 256>>>(
            query, pwc, cw_W + (size_t)i * D * AD, cw_b + (size_t)i * AD,
            pcom, nullptr, AD, D, 0, 0, 0);
        l2norm256_kernel<<<Bb * NQ, 256>>>(pcom);

        // smooth branch
        gemm_nn_kernel<0, 1><<<dim3(1, 256, 1), 256>>>(
            pcom, nullptr, sw_W1 + (size_t)i * AD * HD, sw_b1 + (size_t)i * HD,
            psh, nullptr, HD, AD, 0, 0, 0);
        sw_reduce_kernel<<<Bb * NQ / 8, 256>>>(psh, sw_W2 + (size_t)i * HD, sw_b2 + i, psm);

        // matrix branch
        gemm_nn_kernel<0, 1><<<dim3(4, 256, 1), 256>>>(
            pcom, nullptr, mw_W1 + (size_t)i * AD * MD, mw_b1 + (size_t)i * MD,
            ph1, nullptr, MD, AD, 0, 0, 0);
        gemm_nn_kernel<0, 2><<<dim3(8, 256, 1), 256>>>(
            ph1, nullptr, mw_W2 + (size_t)i * MD * D, mw_b2 + (size_t)i * D,
            pmat, pmat, D, MD, 0, 0, 0);
    }

    // final attention scan, writing attn and wc straight into d_out
    gemm_s_kernel<<<dim3(2, 128), 256>>>(ctx, query, pmat, pS);
    rownorm_kernel<<<Bb * NC, 256>>>(pS, pinvn);
    softmax_kernel<<<dim3(8, 128), 256>>>(pS, pinvn, psm, out_attn);
    gemm_nn_kernel<0, 0><<<dim3(8, 2, 128), 256>>>(
        out_attn, nullptr, ctx, nullptr, out_wc, nullptr,
        D, NC, (size_t)NQ * NC, (size_t)NC * D, (size_t)NQ * D);

    cudaMemcpyAsync(out_q, query, (size_t)Bb * NQ * D * sizeof(float),
                    cudaMemcpyDeviceToDevice, 0);
}